// round 13
// baseline (speedup 1.0000x reference)
#include <cuda_runtime.h>
#include <cstdint>

#define FULLMASK 0xFFFFFFFFu

// -------- precomputed tables (__device__ globals) --------
__device__ uint32_t g_fcb[720];    // fc sign bits [k][72 words]
__device__ uint4    g_sc2[32768];  // [idx15] strip c2 per-ch mismatch (0..48)
__device__ uint4    g_T01[1 << 20];// [20-bit patch, col-major 4x5] per-ch (m_c0+m_c1), 0..96

// ---------------------------------------------------------------------------
// Single prep kernel: 4314 blocks x 256 threads, no inter-block dependency.
// Blocks 0..4095: T01. 4096..4223: Sc2. 4224..4313: fcb.
// Table blocks rebuild lut1/w2c locally via coalesced ballot packing (wide,
// latency-flat — no serial load chains).
// ---------------------------------------------------------------------------
__global__ void bnn_prep(const float* __restrict__ w1,
                         const float* __restrict__ w2,
                         const float* __restrict__ fcw) {
    const int t  = threadIdx.x;
    const int bk = blockIdx.x;
    const int wid = t >> 5, lane = t & 31;
    if (bk >= 4224) {               // fcb: coalesced warp ballot
        int wd = (bk - 4224) * 8 + wid;          // 0..719
        uint32_t m = __ballot_sync(FULLMASK, fcw[wd * 32 + lane] > 0.f);
        if (lane == 0) g_fcb[wd] = m;
        return;
    }
    __shared__ uint32_t           w1bits[5];     // 144 sign bits of w1
    __shared__ uint32_t           w2bits[72];    // 2304 sign bits of w2
    __shared__ uint32_t           w1p[16];
    __shared__ uint16_t           lut1[512];
    __shared__ unsigned long long w2c[48];

    {   // coalesced sign packing
        uint32_t m = __ballot_sync(FULLMASK, t < 144 && w1[t < 144 ? t : 0] > 0.f);
        if (lane == 0 && wid < 5) w1bits[wid] = m;
        #pragma unroll
        for (int k = 0; k < 9; k++) {
            uint32_t mm = __ballot_sync(FULLMASK, w2[k * 256 + t] > 0.f);
            if (lane == 0) w2bits[k * 8 + wid] = mm;
        }
    }
    __syncthreads();
    if (t < 16) {                   // w1p[o] = bits [9o..9o+9)
        uint32_t b = 0;
        #pragma unroll
        for (int rc = 0; rc < 9; rc++) {
            int bi = t * 9 + rc;
            b |= ((w1bits[bi >> 5] >> (bi & 31)) & 1u) << rc;
        }
        w1p[t] = b;
    }
    if (t >= 32 && t < 80) {        // w2c[c*16+o]: bit r*16+i = sign(w2[o][i][r][c])
        int c = (t - 32) >> 4, o = (t - 32) & 15;
        unsigned long long v = 0;
        #pragma unroll
        for (int r = 0; r < 3; r++)
            #pragma unroll
            for (int i = 0; i < 16; i++) {
                int bi = ((o * 16 + i) * 3 + r) * 3 + c;
                v |= (unsigned long long)((w2bits[bi >> 5] >> (bi & 31)) & 1u)
                     << (r * 16 + i);
            }
        w2c[t - 32] = v;
    }
    __syncthreads();
    #pragma unroll
    for (int q = 0; q < 2; q++) {   // conv1 LUT: 2 entries/thread
        int e = q * 256 + t;
        uint32_t mask = 0;
        #pragma unroll
        for (int o = 0; o < 16; o++) {
            int m = __popc((uint32_t)e ^ w1p[o]);  // 9 odd terms; never 0
            if (m <= 4) mask |= (1u << o);
        }
        lut1[e] = (uint16_t)mask;
    }
    __syncthreads();

    if (bk < 4096) {                // T01
        int p = bk * 256 + t;       // 20-bit patch (col-major 4x5)
        uint32_t c0 = p & 31, c1 = (p >> 5) & 31, c2 = (p >> 10) & 31, c3 = (p >> 15) & 31;
        unsigned long long V0 = 0, V1 = 0;
        #pragma unroll
        for (int r = 0; r < 3; r++) {
            uint32_t b0 = (c0 >> r) & 7u, b1 = (c1 >> r) & 7u,
                     b2 = (c2 >> r) & 7u, b3 = (c3 >> r) & 7u;
            uint32_t e0 = (b0 & 1) | ((b0 & 2) << 2) | ((b0 & 4) << 4);
            uint32_t e1 = (b1 & 1) | ((b1 & 2) << 2) | ((b1 & 4) << 4);
            uint32_t e2 = (b2 & 1) | ((b2 & 2) << 2) | ((b2 & 4) << 4);
            uint32_t e3 = (b3 & 1) | ((b3 & 2) << 2) | ((b3 & 4) << 4);
            V0 |= (unsigned long long)lut1[e0 | (e1 << 1) | (e2 << 2)] << (16 * r);
            V1 |= (unsigned long long)lut1[e1 | (e2 << 1) | (e3 << 2)] << (16 * r);
        }
        uint32_t w[4];
        #pragma unroll
        for (int g = 0; g < 4; g++) {
            uint32_t word = 0;
            #pragma unroll
            for (int j = 0; j < 4; j++) {
                int o = g * 4 + j;
                int m = __popcll(V0 ^ w2c[o]) + __popcll(V1 ^ w2c[16 + o]);  // 0..96
                word |= (uint32_t)m << (8 * j);
            }
            w[g] = word;
        }
        g_T01[p] = make_uint4(w[0], w[1], w[2], w[3]);
    } else {                        // Sc2
        int idx = (bk - 4096) * 256 + t;     // 15-bit patch
        uint32_t c0 = idx & 31, c1 = (idx >> 5) & 31, c2 = (idx >> 10) & 31;
        unsigned long long V = 0;
        #pragma unroll
        for (int r = 0; r < 3; r++) {
            uint32_t b0 = (c0 >> r) & 7u, b1 = (c1 >> r) & 7u, b2 = (c2 >> r) & 7u;
            uint32_t e0 = (b0 & 1) | ((b0 & 2) << 2) | ((b0 & 4) << 4);
            uint32_t e1 = (b1 & 1) | ((b1 & 2) << 2) | ((b1 & 4) << 4);
            uint32_t e2 = (b2 & 1) | ((b2 & 2) << 2) | ((b2 & 4) << 4);
            V |= (unsigned long long)lut1[e0 | (e1 << 1) | (e2 << 2)] << (16 * r);
        }
        uint32_t w[4];
        #pragma unroll
        for (int g = 0; g < 4; g++) {
            uint32_t word = 0;
            #pragma unroll
            for (int j = 0; j < 4; j++) {
                int m = __popcll(V ^ w2c[32 + g * 4 + j]);   // 0..48
                word |= (uint32_t)m << (8 * j);
            }
            w[g] = word;
        }
        g_sc2[idx] = make_uint4(w[0], w[1], w[2], w[3]);
    }
}

// ---------------------------------------------------------------------------
// Main kernel: one image per CTA, 288 threads (9 warps). 4-gather conv core
// (measured-best variant).
// ---------------------------------------------------------------------------
__global__ __launch_bounds__(288, 5) void bnn_kernel(const float* __restrict__ x,
                                                     float* __restrict__ out) {
    __shared__ uint32_t xb[28];      // row bitmaps (bit j = col j)
    __shared__ uint32_t xcol[28];    // col bitmaps (bit r = row r)
    __shared__ uint32_t s3c[576];    // class bytes [p*16+o]: 0=neg,1=zero,2=pos
    __shared__ uint32_t Pw[72], Mw[72];
    __shared__ int      lg[10];

    const int tid  = threadIdx.x;
    const int warp = tid >> 5;
    const int lane = tid & 31;
    const int b    = blockIdx.x;
    const float* xi = x + (size_t)b * 784;

    // ---- threshold + bit-pack rows (x >= 0.2 -> +1) ----
    for (int row = warp; row < 28; row += 9) {
        int act = (lane < 28);
        float v = act ? xi[row * 28 + lane] : -1.f;
        uint32_t m = __ballot_sync(FULLMASK, act && (v >= 0.2f));
        if (lane == 0) xb[row] = m;
    }
    __syncthreads();

    // ---- transpose to column bitmaps via ballots ----
    for (int col = warp; col < 28; col += 9) {
        uint32_t bit = (lane < 28) ? ((xb[lane] >> col) & 1u) : 0u;
        uint32_t m = __ballot_sync(FULLMASK, bit);
        if (lane == 0) xcol[col] = m;
    }
    __syncthreads();

    // ---- conv1+conv2+sign via 2 table gathers per output, pool + sign ----
    {
        int blk = tid >> 1;                 // 0..143 pooled pixel
        int dx  = tid & 1;                  // pool column
        int pi = blk / 12, pj = blk - pi * 12;
        int y0 = pi * 2, x0 = pj * 2 + dx;

        uint32_t c6_0 = (xcol[x0]     >> y0) & 63u;
        uint32_t c6_1 = (xcol[x0 + 1] >> y0) & 63u;
        uint32_t c6_2 = (xcol[x0 + 2] >> y0) & 63u;
        uint32_t c6_3 = (xcol[x0 + 3] >> y0) & 63u;
        uint32_t c6_4 = (xcol[x0 + 4] >> y0) & 63u;

        uint32_t iA0 = (c6_0 & 31) | ((c6_1 & 31) << 5) | ((c6_2 & 31) << 10) | ((c6_3 & 31) << 15);
        uint32_t iB0 = (c6_2 & 31) | ((c6_3 & 31) << 5) | ((c6_4 & 31) << 10);
        uint32_t iA1 = (c6_0 >> 1) | ((c6_1 >> 1) << 5) | ((c6_2 >> 1) << 10) | ((c6_3 >> 1) << 15);
        uint32_t iB1 = (c6_2 >> 1) | ((c6_3 >> 1) << 5) | ((c6_4 >> 1) << 10);

        uint4 eA0 = g_T01[iA0];
        uint4 eB0 = g_sc2[iB0];
        uint4 eA1 = g_T01[iA1];
        uint4 eB1 = g_sc2[iB1];

        uint32_t a0[4], a1[4];   // per-channel total mismatch (bytes, 0..144)
        a0[0] = eA0.x + eB0.x; a0[1] = eA0.y + eB0.y; a0[2] = eA0.z + eB0.z; a0[3] = eA0.w + eB0.w;
        a1[0] = eA1.x + eB1.x; a1[1] = eA1.y + eB1.y; a1[2] = eA1.z + eB1.z; a1[3] = eA1.w + eB1.w;

        const uint32_t M7 = 0x80808080u;
        #pragma unroll
        for (int g = 0; g < 4; g++) {
            uint32_t m0 = a0[g], m1 = a1[g];      // sign = sgn(144-2m)
            uint32_t ge0 = (m0 + 0x38383838u);    // bit7: m >= 72
            uint32_t gt0 = (m0 + 0x37373737u);    // bit7: m >  72
            uint32_t ge1 = (m1 + 0x38383838u);
            uint32_t gt1 = (m1 + 0x37373737u);
            uint32_t pos = (((~ge0) & M7) >> 7) + (((~ge1) & M7) >> 7);
            uint32_t neg = ((gt0 & M7) >> 7) + ((gt1 & M7) >> 7);
            uint32_t t   = pos + 0x02020202u - neg;                      // bias 2
            uint32_t t4b = t + __shfl_xor_sync(FULLMASK, t, 1);          // bias 4
            uint32_t gtm = (t4b + 0x7B7B7B7Bu) & M7;                     // t4 > 0
            uint32_t gem = (t4b + 0x7C7C7C7Cu) & M7;                     // t4 >= 0
            uint32_t cls = (gtm >> 7) + (0x01010101u - (((~gem) & M7) >> 7));
            if (dx == 0) s3c[blk * 4 + g] = cls;  // byte o: 2=pos,1=zero,0=neg
        }
    }
    __syncthreads();

    // ---- pack ternary s3 into plus/minus bitmasks (fc order o*144+p) ----
    {
        const uint8_t* s3b = (const uint8_t*)s3c;
        int o0 = tid / 144;                 // 0 or 1
        int p  = tid - o0 * 144;
        int base = p * 16 + o0;
        #pragma unroll
        for (int it = 0; it < 8; it++) {
            uint32_t v = s3b[base + 2 * it];
            uint32_t Pm = __ballot_sync(FULLMASK, v == 2u);
            uint32_t Mm = __ballot_sync(FULLMASK, v == 0u);
            if (lane == 0) { Pw[it * 9 + warp] = Pm; Mw[it * 9 + warp] = Mm; }
        }
    }
    __syncthreads();

    // ---- FC via AND+popcount ----
    for (int rep = 0; rep < 2; rep++) {
        if (rep == 1 && warp != 0) break;
        int k = (rep == 0) ? warp : 9;
        int acc = 0, c = 0;
        for (int wd = lane; wd < 72; wd += 32) {
            uint32_t p = Pw[wd], m = Mw[wd], wk = g_fcb[k * 72 + wd];
            acc += __popc(p & wk) - __popc(m & wk);
            c   += __popc(m) - __popc(p);
        }
        #pragma unroll
        for (int off = 16; off; off >>= 1) {
            acc += __shfl_xor_sync(FULLMASK, acc, off);
            c   += __shfl_xor_sync(FULLMASK, c, off);
        }
        if (lane == 0) lg[k] = 2 * acc + c;
    }
    __syncthreads();

    // ---- log_softmax over 10 logits ----
    if (warp == 0) {
        float v = (lane < 10) ? (float)lg[lane] : -3.0e38f;
        float mx = v;
        #pragma unroll
        for (int off = 16; off; off >>= 1) mx = fmaxf(mx, __shfl_xor_sync(FULLMASK, mx, off));
        float e = (lane < 10) ? expf(v - mx) : 0.f;
        float s = e;
        #pragma unroll
        for (int off = 16; off; off >>= 1) s += __shfl_xor_sync(FULLMASK, s, off);
        if (lane < 10) out[b * 10 + lane] = v - mx - logf(s);
    }
}

// ---------------------------------------------------------------------------
extern "C" void kernel_launch(void* const* d_in, const int* in_sizes, int n_in,
                              void* d_out, int out_size) {
    const float* x   = (const float*)d_in[0];   // [8192,1,28,28]
    const float* w1  = (const float*)d_in[1];   // [16,1,3,3]
    const float* w2  = (const float*)d_in[2];   // [16,16,3,3]
    const float* fcw = (const float*)d_in[3];   // [10,2304]
    float* out = (float*)d_out;                 // [8192,10]

    int batch = in_sizes[0] / 784;

    bnn_prep<<<4314, 256>>>(w1, w2, fcw);
    bnn_kernel<<<batch, 288>>>(x, out);
}

// round 16
// speedup vs baseline: 1.2863x; 1.2863x over previous
#include <cuda_runtime.h>
#include <cstdint>

#define FULLMASK 0xFFFFFFFFu

// -------- precomputed tables (__device__ globals) --------
__device__ uint32_t g_fcb[720];       // fc sign bits [k][72 words]
__device__ uint4    g_sc[3 * 32768];  // col-major strip tables: [c][idx15] -> 16B
                                      //   per-channel mismatch (0..48) of strip c
__device__ uint4    g_T01[1 << 20];   // [20-bit patch: 4 cols x 5 rows, col-major]
                                      //   -> per-channel (m_c0 + m_c1), 0..96

// ---------------------------------------------------------------------------
// prep_a: build col-major strip tables + fc bit-pack. 474 blocks x 256 thr.
// Blocks 0..383: strip tables. Blocks 384..473: fcb (8 words per block).
// Prologue uses coalesced ballot packing (no serial load chains).
// idx15 layout: bits [5c..5c+5) = column c, bit k within = patch row k.
// ---------------------------------------------------------------------------
__global__ void bnn_prep_a(const float* __restrict__ w1,
                           const float* __restrict__ w2,
                           const float* __restrict__ fcw) {
    const int t = threadIdx.x;
    const int wid = t >> 5, lane = t & 31;
    if (blockIdx.x >= 384) {        // fcb: coalesced warp ballot, 8 warps/block
        int wd = (blockIdx.x - 384) * 8 + wid;      // 0..719
        uint32_t m = __ballot_sync(FULLMASK, fcw[wd * 32 + lane] > 0.f);
        if (lane == 0) g_fcb[wd] = m;
        return;
    }
    __shared__ uint32_t           w1bits[5];     // 144 sign bits of w1
    __shared__ uint32_t           w2bits[72];    // 2304 sign bits of w2
    __shared__ uint32_t           w1p[16];
    __shared__ uint16_t           lut1[512];
    __shared__ unsigned long long w2c[48];

    {   // coalesced sign packing via ballots
        uint32_t m = __ballot_sync(FULLMASK, (t < 144) && (w1[t < 144 ? t : 0] > 0.f));
        if (lane == 0 && wid < 5) w1bits[wid] = m;
        #pragma unroll
        for (int k = 0; k < 9; k++) {
            uint32_t mm = __ballot_sync(FULLMASK, w2[k * 256 + t] > 0.f);
            if (lane == 0) w2bits[k * 8 + wid] = mm;
        }
    }
    __syncthreads();
    if (t < 16) {                   // w1p[o] = bits [9o..9o+9)
        uint32_t b = 0;
        #pragma unroll
        for (int rc = 0; rc < 9; rc++) {
            int bi = t * 9 + rc;
            b |= ((w1bits[bi >> 5] >> (bi & 31)) & 1u) << rc;
        }
        w1p[t] = b;
    }
    if (t >= 32 && t < 80) {        // w2c[c*16+o]: bit r*16+i = sign(w2[o][i][r][c])
        int c = (t - 32) >> 4, o = (t - 32) & 15;
        unsigned long long v = 0;
        #pragma unroll
        for (int r = 0; r < 3; r++)
            #pragma unroll
            for (int i = 0; i < 16; i++) {
                int bi = ((o * 16 + i) * 3 + r) * 3 + c;
                v |= (unsigned long long)((w2bits[bi >> 5] >> (bi & 31)) & 1u)
                     << (r * 16 + i);
            }
        w2c[t - 32] = v;
    }
    __syncthreads();
    #pragma unroll
    for (int q = 0; q < 2; q++) {   // conv1 LUT: 2 entries/thread
        int e = q * 256 + t;
        uint32_t mask = 0;
        #pragma unroll
        for (int o = 0; o < 16; o++) {
            int m = __popc((uint32_t)e ^ w1p[o]);  // 9 odd terms; never 0
            if (m <= 4) mask |= (1u << o);
        }
        lut1[e] = (uint16_t)mask;
    }
    __syncthreads();

    int c   = blockIdx.x >> 7;                 // 0..2 (weight column)
    int idx = ((blockIdx.x & 127) << 8) + t;   // 15-bit col-major patch
    uint32_t col0 = idx & 31, col1 = (idx >> 5) & 31, col2 = (idx >> 10) & 31;
    unsigned long long V = 0;   // s1 sign masks rows 0..2 (bit r*16+i)
    #pragma unroll
    for (int r = 0; r < 3; r++) {
        uint32_t b0 = (col0 >> r) & 7u, b1 = (col1 >> r) & 7u, b2 = (col2 >> r) & 7u;
        uint32_t i9 = ((b0 & 1) | ((b0 & 2) << 2) | ((b0 & 4) << 4))
                    | (((b1 & 1) | ((b1 & 2) << 2) | ((b1 & 4) << 4)) << 1)
                    | (((b2 & 1) | ((b2 & 2) << 2) | ((b2 & 4) << 4)) << 2);
        V |= (unsigned long long)lut1[i9] << (16 * r);
    }
    uint32_t w[4];
    #pragma unroll
    for (int g = 0; g < 4; g++) {
        uint32_t word = 0;
        #pragma unroll
        for (int j = 0; j < 4; j++) {
            int m = __popcll(V ^ w2c[c * 16 + g * 4 + j]);  // 0..48
            word |= (uint32_t)m << (8 * j);
        }
        w[g] = word;
    }
    g_sc[(c << 15) + idx] = make_uint4(w[0], w[1], w[2], w[3]);
}

// ---------------------------------------------------------------------------
// prep_b: T01[p] = Sc0[cols 0-2] + Sc1[cols 1-3]. Fully coalesced.
// ---------------------------------------------------------------------------
__global__ void bnn_prep_b() {
    int p = blockIdx.x * 256 + threadIdx.x;        // 20-bit patch index
    uint4 a = g_sc[p & 32767];
    uint4 b = g_sc[32768 + (p >> 5)];
    // byte lanes <= 48+48 = 96: carry-free word adds
    g_T01[p] = make_uint4(a.x + b.x, a.y + b.y, a.z + b.z, a.w + b.w);
}

// ---------------------------------------------------------------------------
// Main kernel: one image per CTA, 288 threads (9 warps). 4-gather conv core.
// ---------------------------------------------------------------------------
__global__ __launch_bounds__(288, 5) void bnn_kernel(const float* __restrict__ x,
                                                     float* __restrict__ out) {
    __shared__ uint32_t xb[28];      // row bitmaps (bit j = col j)
    __shared__ uint32_t xcol[28];    // col bitmaps (bit r = row r)
    __shared__ uint32_t s3c[576];    // class bytes [p*16+o]: 0=neg,1=zero,2=pos
    __shared__ uint32_t Pw[72], Mw[72];
    __shared__ int      lg[10];

    const int tid  = threadIdx.x;
    const int warp = tid >> 5;
    const int lane = tid & 31;
    const int b    = blockIdx.x;
    const float* xi = x + (size_t)b * 784;

    // ---- threshold + bit-pack rows (x >= 0.2 -> +1) ----
    for (int row = warp; row < 28; row += 9) {
        int act = (lane < 28);
        float v = act ? xi[row * 28 + lane] : -1.f;
        uint32_t m = __ballot_sync(FULLMASK, act && (v >= 0.2f));
        if (lane == 0) xb[row] = m;
    }
    __syncthreads();

    // ---- transpose to column bitmaps via ballots ----
    for (int col = warp; col < 28; col += 9) {
        uint32_t bit = (lane < 28) ? ((xb[lane] >> col) & 1u) : 0u;
        uint32_t m = __ballot_sync(FULLMASK, bit);
        if (lane == 0) xcol[col] = m;
    }
    __syncthreads();

    // ---- conv1+conv2+sign via 2 table gathers per output, pool + sign ----
    {
        int blk = tid >> 1;                 // 0..143 pooled pixel
        int dx  = tid & 1;                  // pool column
        int pi = blk / 12, pj = blk - pi * 12;
        int y0 = pi * 2, x0 = pj * 2 + dx;

        uint32_t c6_0 = (xcol[x0]     >> y0) & 63u;
        uint32_t c6_1 = (xcol[x0 + 1] >> y0) & 63u;
        uint32_t c6_2 = (xcol[x0 + 2] >> y0) & 63u;
        uint32_t c6_3 = (xcol[x0 + 3] >> y0) & 63u;
        uint32_t c6_4 = (xcol[x0 + 4] >> y0) & 63u;

        uint32_t iA0 = (c6_0 & 31) | ((c6_1 & 31) << 5) | ((c6_2 & 31) << 10) | ((c6_3 & 31) << 15);
        uint32_t iB0 = (c6_2 & 31) | ((c6_3 & 31) << 5) | ((c6_4 & 31) << 10);
        uint32_t iA1 = (c6_0 >> 1) | ((c6_1 >> 1) << 5) | ((c6_2 >> 1) << 10) | ((c6_3 >> 1) << 15);
        uint32_t iB1 = (c6_2 >> 1) | ((c6_3 >> 1) << 5) | ((c6_4 >> 1) << 10);

        uint4 eA0 = g_T01[iA0];
        uint4 eB0 = g_sc[2 * 32768 + iB0];
        uint4 eA1 = g_T01[iA1];
        uint4 eB1 = g_sc[2 * 32768 + iB1];

        uint32_t a0[4], a1[4];   // per-channel total mismatch (bytes, 0..144)
        a0[0] = eA0.x + eB0.x; a0[1] = eA0.y + eB0.y; a0[2] = eA0.z + eB0.z; a0[3] = eA0.w + eB0.w;
        a1[0] = eA1.x + eB1.x; a1[1] = eA1.y + eB1.y; a1[2] = eA1.z + eB1.z; a1[3] = eA1.w + eB1.w;

        const uint32_t M7 = 0x80808080u;
        #pragma unroll
        for (int g = 0; g < 4; g++) {
            uint32_t m0 = a0[g], m1 = a1[g];      // sign = sgn(144-2m)
            uint32_t ge0 = (m0 + 0x38383838u);    // bit7: m >= 72
            uint32_t gt0 = (m0 + 0x37373737u);    // bit7: m >  72
            uint32_t ge1 = (m1 + 0x38383838u);
            uint32_t gt1 = (m1 + 0x37373737u);
            uint32_t pos = (((~ge0) & M7) >> 7) + (((~ge1) & M7) >> 7);
            uint32_t neg = ((gt0 & M7) >> 7) + ((gt1 & M7) >> 7);
            uint32_t t   = pos + 0x02020202u - neg;                      // bias 2
            uint32_t t4b = t + __shfl_xor_sync(FULLMASK, t, 1);          // bias 4
            uint32_t gtm = (t4b + 0x7B7B7B7Bu) & M7;                     // t4 > 0
            uint32_t gem = (t4b + 0x7C7C7C7Cu) & M7;                     // t4 >= 0
            uint32_t cls = (gtm >> 7) + (0x01010101u - (((~gem) & M7) >> 7));
            if (dx == 0) s3c[blk * 4 + g] = cls;  // byte o: 2=pos,1=zero,0=neg
        }
    }
    __syncthreads();

    // ---- pack ternary s3 into plus/minus bitmasks (fc order o*144+p) ----
    {
        const uint8_t* s3b = (const uint8_t*)s3c;
        int o0 = tid / 144;                 // 0 or 1
        int p  = tid - o0 * 144;
        int base = p * 16 + o0;
        #pragma unroll
        for (int it = 0; it < 8; it++) {
            uint32_t v = s3b[base + 2 * it];
            uint32_t Pm = __ballot_sync(FULLMASK, v == 2u);
            uint32_t Mm = __ballot_sync(FULLMASK, v == 0u);
            if (lane == 0) { Pw[it * 9 + warp] = Pm; Mw[it * 9 + warp] = Mm; }
        }
    }
    __syncthreads();

    // ---- FC via AND+popcount ----
    for (int rep = 0; rep < 2; rep++) {
        if (rep == 1 && warp != 0) break;
        int k = (rep == 0) ? warp : 9;
        int acc = 0, c = 0;
        for (int wd = lane; wd < 72; wd += 32) {
            uint32_t p = Pw[wd], m = Mw[wd], wk = g_fcb[k * 72 + wd];
            acc += __popc(p & wk) - __popc(m & wk);
            c   += __popc(m) - __popc(p);
        }
        #pragma unroll
        for (int off = 16; off; off >>= 1) {
            acc += __shfl_xor_sync(FULLMASK, acc, off);
            c   += __shfl_xor_sync(FULLMASK, c, off);
        }
        if (lane == 0) lg[k] = 2 * acc + c;
    }
    __syncthreads();

    // ---- log_softmax over 10 logits ----
    if (warp == 0) {
        float v = (lane < 10) ? (float)lg[lane] : -3.0e38f;
        float mx = v;
        #pragma unroll
        for (int off = 16; off; off >>= 1) mx = fmaxf(mx, __shfl_xor_sync(FULLMASK, mx, off));
        float e = (lane < 10) ? expf(v - mx) : 0.f;
        float s = e;
        #pragma unroll
        for (int off = 16; off; off >>= 1) s += __shfl_xor_sync(FULLMASK, s, off);
        if (lane < 10) out[b * 10 + lane] = v - mx - logf(s);
    }
}

// ---------------------------------------------------------------------------
extern "C" void kernel_launch(void* const* d_in, const int* in_sizes, int n_in,
                              void* d_out, int out_size) {
    const float* x   = (const float*)d_in[0];   // [8192,1,28,28]
    const float* w1  = (const float*)d_in[1];   // [16,1,3,3]
    const float* w2  = (const float*)d_in[2];   // [16,16,3,3]
    const float* fcw = (const float*)d_in[3];   // [10,2304]
    float* out = (float*)d_out;                 // [8192,10]

    int batch = in_sizes[0] / 784;

    bnn_prep_a<<<474, 256>>>(w1, w2, fcw);
    bnn_prep_b<<<4096, 256>>>();
    bnn_kernel<<<batch, 288>>>(x, out);
}

// round 17
// speedup vs baseline: 1.3154x; 1.0227x over previous
#include <cuda_runtime.h>
#include <cstdint>

#define FULLMASK 0xFFFFFFFFu

// -------- precomputed tables (__device__ globals) --------
__device__ uint32_t g_fcb[720];       // fc sign bits [k][72 words]
__device__ uint4    g_sc[3 * 32768];  // col-major strip tables: [c][idx15] -> 16B
                                      //   per-channel mismatch (0..48) of strip c
__device__ uint4    g_T01[1 << 20];   // [20-bit patch: 4 cols x 5 rows, col-major]
                                      //   -> per-channel (m_c0 + m_c1), 0..96

// ---------------------------------------------------------------------------
// prep_a: build col-major strip tables + fc bit-pack. 474 blocks x 256 thr.
// (byte-identical to the 78.0us round-16 version)
// ---------------------------------------------------------------------------
__global__ void bnn_prep_a(const float* __restrict__ w1,
                           const float* __restrict__ w2,
                           const float* __restrict__ fcw) {
    const int t = threadIdx.x;
    const int wid = t >> 5, lane = t & 31;
    if (blockIdx.x >= 384) {        // fcb: coalesced warp ballot, 8 warps/block
        int wd = (blockIdx.x - 384) * 8 + wid;      // 0..719
        uint32_t m = __ballot_sync(FULLMASK, fcw[wd * 32 + lane] > 0.f);
        if (lane == 0) g_fcb[wd] = m;
        return;
    }
    __shared__ uint32_t           w1bits[5];
    __shared__ uint32_t           w2bits[72];
    __shared__ uint32_t           w1p[16];
    __shared__ uint16_t           lut1[512];
    __shared__ unsigned long long w2c[48];

    {   // coalesced sign packing via ballots
        uint32_t m = __ballot_sync(FULLMASK, (t < 144) && (w1[t < 144 ? t : 0] > 0.f));
        if (lane == 0 && wid < 5) w1bits[wid] = m;
        #pragma unroll
        for (int k = 0; k < 9; k++) {
            uint32_t mm = __ballot_sync(FULLMASK, w2[k * 256 + t] > 0.f);
            if (lane == 0) w2bits[k * 8 + wid] = mm;
        }
    }
    __syncthreads();
    if (t < 16) {
        uint32_t b = 0;
        #pragma unroll
        for (int rc = 0; rc < 9; rc++) {
            int bi = t * 9 + rc;
            b |= ((w1bits[bi >> 5] >> (bi & 31)) & 1u) << rc;
        }
        w1p[t] = b;
    }
    if (t >= 32 && t < 80) {
        int c = (t - 32) >> 4, o = (t - 32) & 15;
        unsigned long long v = 0;
        #pragma unroll
        for (int r = 0; r < 3; r++)
            #pragma unroll
            for (int i = 0; i < 16; i++) {
                int bi = ((o * 16 + i) * 3 + r) * 3 + c;
                v |= (unsigned long long)((w2bits[bi >> 5] >> (bi & 31)) & 1u)
                     << (r * 16 + i);
            }
        w2c[t - 32] = v;
    }
    __syncthreads();
    #pragma unroll
    for (int q = 0; q < 2; q++) {
        int e = q * 256 + t;
        uint32_t mask = 0;
        #pragma unroll
        for (int o = 0; o < 16; o++) {
            int m = __popc((uint32_t)e ^ w1p[o]);
            if (m <= 4) mask |= (1u << o);
        }
        lut1[e] = (uint16_t)mask;
    }
    __syncthreads();

    int c   = blockIdx.x >> 7;
    int idx = ((blockIdx.x & 127) << 8) + t;
    uint32_t col0 = idx & 31, col1 = (idx >> 5) & 31, col2 = (idx >> 10) & 31;
    unsigned long long V = 0;
    #pragma unroll
    for (int r = 0; r < 3; r++) {
        uint32_t b0 = (col0 >> r) & 7u, b1 = (col1 >> r) & 7u, b2 = (col2 >> r) & 7u;
        uint32_t i9 = ((b0 & 1) | ((b0 & 2) << 2) | ((b0 & 4) << 4))
                    | (((b1 & 1) | ((b1 & 2) << 2) | ((b1 & 4) << 4)) << 1)
                    | (((b2 & 1) | ((b2 & 2) << 2) | ((b2 & 4) << 4)) << 2);
        V |= (unsigned long long)lut1[i9] << (16 * r);
    }
    uint32_t w[4];
    #pragma unroll
    for (int g = 0; g < 4; g++) {
        uint32_t word = 0;
        #pragma unroll
        for (int j = 0; j < 4; j++) {
            int m = __popcll(V ^ w2c[c * 16 + g * 4 + j]);
            word |= (uint32_t)m << (8 * j);
        }
        w[g] = word;
    }
    g_sc[(c << 15) + idx] = make_uint4(w[0], w[1], w[2], w[3]);
}

// ---------------------------------------------------------------------------
// prep_b: T01[p] = Sc0[cols 0-2] + Sc1[cols 1-3]. Fully coalesced.
// ---------------------------------------------------------------------------
__global__ void bnn_prep_b() {
    int p = blockIdx.x * 256 + threadIdx.x;
    uint4 a = g_sc[p & 32767];
    uint4 b = g_sc[32768 + (p >> 5)];
    g_T01[p] = make_uint4(a.x + b.x, a.y + b.y, a.z + b.z, a.w + b.w);
}

// ---------------------------------------------------------------------------
// Main kernel: one image per CTA, 288 threads (9 warps).
// Conv core: split-word gathers — 4 lanes share each 16B table entry, so each
// LDG.32 touches only 8 sectors (cross-LDG wavefront rate instead of replays).
// ---------------------------------------------------------------------------
__global__ __launch_bounds__(288, 5) void bnn_kernel(const float* __restrict__ x,
                                                     float* __restrict__ out) {
    __shared__ uint32_t xb[28];      // row bitmaps (bit j = col j)
    __shared__ uint32_t xcol[28];    // col bitmaps (bit r = row r)
    __shared__ uint32_t s3c[576];    // class bytes [p*16+o]: 0=neg,1=zero,2=pos
    __shared__ uint32_t Pw[72], Mw[72];
    __shared__ int      lg[10];

    const int tid  = threadIdx.x;
    const int warp = tid >> 5;
    const int lane = tid & 31;
    const int b    = blockIdx.x;
    const float* xi = x + (size_t)b * 784;

    // ---- threshold + bit-pack rows (x >= 0.2 -> +1) ----
    for (int row = warp; row < 28; row += 9) {
        int act = (lane < 28);
        float v = act ? xi[row * 28 + lane] : -1.f;
        uint32_t m = __ballot_sync(FULLMASK, act && (v >= 0.2f));
        if (lane == 0) xb[row] = m;
    }
    __syncthreads();

    // ---- transpose to column bitmaps via ballots ----
    for (int col = warp; col < 28; col += 9) {
        uint32_t bit = (lane < 28) ? ((xb[lane] >> col) & 1u) : 0u;
        uint32_t m = __ballot_sync(FULLMASK, bit);
        if (lane == 0) xcol[col] = m;
    }
    __syncthreads();

    // ---- conv1+conv2+sign via split-word table gathers, pool + sign ----
    {
        const uint32_t* T01w = (const uint32_t*)g_T01;
        const uint32_t* Sc2w = (const uint32_t*)(g_sc + 2 * 32768);
        const uint32_t  M7   = 0x80808080u;
        int p  = lane >> 2;          // unit slot within warp-round (0..7)
        int cg = lane & 3;           // channel group / entry word (0..3)
        #pragma unroll
        for (int r = 0; r < 4; r++) {
            int unit = warp * 32 + r * 8 + p;   // 0..287 = (pooled pixel, dx)
            int blk = unit >> 1, dx = unit & 1;
            int pi = blk / 12, pj = blk - pi * 12;
            int y0 = pi * 2, x0 = pj * 2 + dx;

            uint32_t c6_0 = (xcol[x0]     >> y0) & 63u;
            uint32_t c6_1 = (xcol[x0 + 1] >> y0) & 63u;
            uint32_t c6_2 = (xcol[x0 + 2] >> y0) & 63u;
            uint32_t c6_3 = (xcol[x0 + 3] >> y0) & 63u;
            uint32_t c6_4 = (xcol[x0 + 4] >> y0) & 63u;

            // each lane computes ONE index type, shares the rest via shfl
            uint32_t idx;
            if (cg == 0)
                idx = (c6_0 & 31) | ((c6_1 & 31) << 5) | ((c6_2 & 31) << 10) | ((c6_3 & 31) << 15);
            else if (cg == 1)
                idx = (c6_2 & 31) | ((c6_3 & 31) << 5) | ((c6_4 & 31) << 10);
            else if (cg == 2)
                idx = (c6_0 >> 1) | ((c6_1 >> 1) << 5) | ((c6_2 >> 1) << 10) | ((c6_3 >> 1) << 15);
            else
                idx = (c6_2 >> 1) | ((c6_3 >> 1) << 5) | ((c6_4 >> 1) << 10);
            int base = p << 2;
            uint32_t iA0 = __shfl_sync(FULLMASK, idx, base);
            uint32_t iB0 = __shfl_sync(FULLMASK, idx, base + 1);
            uint32_t iA1 = __shfl_sync(FULLMASK, idx, base + 2);
            uint32_t iB1 = __shfl_sync(FULLMASK, idx, base + 3);

            // 4 lanes of a unit load the 4 words of each entry (shared sector)
            uint32_t e0 = T01w[iA0 * 4 + cg];
            uint32_t e1 = Sc2w[iB0 * 4 + cg];
            uint32_t e2 = T01w[iA1 * 4 + cg];
            uint32_t e3 = Sc2w[iB1 * 4 + cg];
            uint32_t m0 = e0 + e1;   // bytes 0..144: total mismatch, 4 channels
            uint32_t m1 = e2 + e3;

            uint32_t ge0 = m0 + 0x38383838u;     // bit7: m >= 72
            uint32_t gt0 = m0 + 0x37373737u;     // bit7: m >  72
            uint32_t ge1 = m1 + 0x38383838u;
            uint32_t gt1 = m1 + 0x37373737u;
            uint32_t pos = (((~ge0) & M7) >> 7) + (((~ge1) & M7) >> 7);
            uint32_t neg = ((gt0 & M7) >> 7) + ((gt1 & M7) >> 7);
            uint32_t t   = pos + 0x02020202u - neg;                 // bias 2
            uint32_t t4b = t + __shfl_xor_sync(FULLMASK, t, 4);     // dx pair; bias 4
            uint32_t gtm = (t4b + 0x7B7B7B7Bu) & M7;                // t4 > 0
            uint32_t gem = (t4b + 0x7C7C7C7Cu) & M7;                // t4 >= 0
            uint32_t cls = (gtm >> 7) + (0x01010101u - (((~gem) & M7) >> 7));
            if (dx == 0) s3c[blk * 4 + cg] = cls;  // byte o: 2=pos,1=zero,0=neg
        }
    }
    __syncthreads();

    // ---- pack ternary s3 into plus/minus bitmasks (fc order o*144+p) ----
    {
        const uint8_t* s3b = (const uint8_t*)s3c;
        int o0 = tid / 144;                 // 0 or 1
        int p  = tid - o0 * 144;
        int base = p * 16 + o0;
        #pragma unroll
        for (int it = 0; it < 8; it++) {
            uint32_t v = s3b[base + 2 * it];
            uint32_t Pm = __ballot_sync(FULLMASK, v == 2u);
            uint32_t Mm = __ballot_sync(FULLMASK, v == 0u);
            if (lane == 0) { Pw[it * 9 + warp] = Pm; Mw[it * 9 + warp] = Mm; }
        }
    }
    __syncthreads();

    // ---- FC via AND+popcount ----
    for (int rep = 0; rep < 2; rep++) {
        if (rep == 1 && warp != 0) break;
        int k = (rep == 0) ? warp : 9;
        int acc = 0, c = 0;
        for (int wd = lane; wd < 72; wd += 32) {
            uint32_t p = Pw[wd], m = Mw[wd], wk = g_fcb[k * 72 + wd];
            acc += __popc(p & wk) - __popc(m & wk);
            c   += __popc(m) - __popc(p);
        }
        #pragma unroll
        for (int off = 16; off; off >>= 1) {
            acc += __shfl_xor_sync(FULLMASK, acc, off);
            c   += __shfl_xor_sync(FULLMASK, c, off);
        }
        if (lane == 0) lg[k] = 2 * acc + c;
    }
    __syncthreads();

    // ---- log_softmax over 10 logits ----
    if (warp == 0) {
        float v = (lane < 10) ? (float)lg[lane] : -3.0e38f;
        float mx = v;
        #pragma unroll
        for (int off = 16; off; off >>= 1) mx = fmaxf(mx, __shfl_xor_sync(FULLMASK, mx, off));
        float e = (lane < 10) ? expf(v - mx) : 0.f;
        float s = e;
        #pragma unroll
        for (int off = 16; off; off >>= 1) s += __shfl_xor_sync(FULLMASK, s, off);
        if (lane < 10) out[b * 10 + lane] = v - mx - logf(s);
    }
}

// ---------------------------------------------------------------------------
extern "C" void kernel_launch(void* const* d_in, const int* in_sizes, int n_in,
                              void* d_out, int out_size) {
    const float* x   = (const float*)d_in[0];   // [8192,1,28,28]
    const float* w1  = (const float*)d_in[1];   // [16,1,3,3]
    const float* w2  = (const float*)d_in[2];   // [16,16,3,3]
    const float* fcw = (const float*)d_in[3];   // [10,2304]
    float* out = (float*)d_out;                 // [8192,10]

    int batch = in_sizes[0] / 784;

    bnn_prep_a<<<474, 256>>>(w1, w2, fcw);
    bnn_prep_b<<<4096, 256>>>();
    bnn_kernel<<<batch, 288>>>(x, out);
}